// round 7
// baseline (speedup 1.0000x reference)
#include <cuda_runtime.h>
#include <cuda_bf16.h>

// Problem constants
#define NN    50000
#define EE    800000
#define INC   128
#define HEADS 8
#define HID   32
#define C1    256
#define OUTC  16
#define NEG   0.2f
#define EPSV  1e-16f

// ---------------- scratch ----------------
__device__ float g_xl1[NN * C1];
__device__ float g_h1 [NN * C1];
__device__ float g_as1[NN * HEADS];
__device__ float g_ad1[NN * HEADS];
__device__ float g_xl2[NN * OUTC];
__device__ float g_as2[NN];
__device__ float g_ad2[NN];
__device__ int   g_deg[NN];
__device__ int   g_rowptr[NN + 1];
__device__ int   g_cursor[NN];
__device__ int   g_col[EE];
__device__ __nv_bfloat16 g_a1 [NN * 512];    // [Xh|Xl|Xh|Xl] per row
__device__ __nv_bfloat16 g_w1t[C1 * 512];    // transposed: [n][Wh|Wh|Wl|Wl]

// ---------------- CSR build ----------------
__global__ void zero_deg_kernel() {
    int i = blockIdx.x * blockDim.x + threadIdx.x;
    for (; i < NN; i += gridDim.x * blockDim.x) g_deg[i] = 0;
}

__global__ void hist_kernel(const int* __restrict__ ei) {
    int i = blockIdx.x * blockDim.x + threadIdx.x;
    if (i < EE) atomicAdd(&g_deg[ei[EE + i]], 1);
}

__global__ void scan_kernel() {
    __shared__ int ssum[1024];
    const int T = 1024;
    int t = threadIdx.x;
    int chunk = (NN + T - 1) / T;
    int b = t * chunk;
    int e = b + chunk; if (e > NN) e = NN;
    int s = 0;
    for (int i = b; i < e; i++) s += g_deg[i];
    ssum[t] = s;
    __syncthreads();
    for (int off = 1; off < T; off <<= 1) {
        int v = (t >= off) ? ssum[t - off] : 0;
        __syncthreads();
        ssum[t] += v;
        __syncthreads();
    }
    int offset = (t == 0) ? 0 : ssum[t - 1];
    if (t == 0) g_rowptr[0] = 0;
    int run = offset;
    for (int i = b; i < e; i++) {
        g_cursor[i] = run;
        run += g_deg[i];
        g_rowptr[i + 1] = run;
    }
}

__global__ void scatter_kernel(const int* __restrict__ ei) {
    int i = blockIdx.x * blockDim.x + threadIdx.x;
    if (i < EE) {
        int d = ei[EE + i];
        int pos = atomicAdd(&g_cursor[d], 1);
        g_col[pos] = ei[i];
    }
}

__device__ __forceinline__ float lrelu(float x) { return x > 0.f ? x : NEG * x; }

// ---------------- fused bf16 split prep (x and W1) ----------------
__global__ void prep_xw_kernel(const float* __restrict__ x, const float* __restrict__ W1) {
    int i = blockIdx.x * blockDim.x + threadIdx.x;
    if (i < NN * INC) {
        int n = i >> 7, k = i & 127;
        float v = x[i];
        __nv_bfloat16 hi = __float2bfloat16(v);
        __nv_bfloat16 lo = __float2bfloat16(v - __bfloat162float(hi));
        __nv_bfloat16* p = g_a1 + (size_t)n * 512 + k;
        p[0]   = hi;
        p[128] = lo;
        p[256] = hi;
        p[384] = lo;
    } else {
        int j = i - NN * INC;
        if (j < INC * C1) {
            int k = j >> 8, n = j & 255;
            float v = W1[j];
            __nv_bfloat16 hi = __float2bfloat16(v);
            __nv_bfloat16 lo = __float2bfloat16(v - __bfloat162float(hi));
            __nv_bfloat16* p = g_w1t + (size_t)n * 512 + k;
            p[0]   = hi;
            p[128] = hi;
            p[256] = lo;
            p[384] = lo;
        }
    }
}

// ---------------- HMMA helper ----------------
__device__ __forceinline__ void mma_bf16(float* d, const unsigned* a, const unsigned* b) {
    asm volatile(
        "mma.sync.aligned.m16n8k16.row.col.f32.bf16.bf16.f32 "
        "{%0,%1,%2,%3}, {%4,%5,%6,%7}, {%8,%9}, {%0,%1,%2,%3};\n"
        : "+f"(d[0]), "+f"(d[1]), "+f"(d[2]), "+f"(d[3])
        : "r"(a[0]), "r"(a[1]), "r"(a[2]), "r"(a[3]), "r"(b[0]), "r"(b[1]));
}

// ---------------- GEMM1 via tensor cores + fused attention logits ----------------
#define AST 72
__global__ void __launch_bounds__(256, 2)
gemm1_mma_kernel(const float* __restrict__ attS, const float* __restrict__ attD) {
    __shared__ __nv_bfloat16 As[128 * AST];
    __shared__ __nv_bfloat16 Bs[64 * AST];
    int tid = threadIdx.x;
    int warp = tid >> 5, lane = tid & 31;
    int wm = warp >> 1, wn = warp & 1;
    int bm = blockIdx.x * 128, bn = blockIdx.y * 64;
    int r = lane >> 2, c = lane & 3;
    int head = (bn + wn * 32) >> 5;

    float aSv[8], aDv[8];
#pragma unroll
    for (int n = 0; n < 4; n++) {
        aSv[n * 2]     = attS[head * HID + n * 8 + 2 * c];
        aSv[n * 2 + 1] = attS[head * HID + n * 8 + 2 * c + 1];
        aDv[n * 2]     = attD[head * HID + n * 8 + 2 * c];
        aDv[n * 2 + 1] = attD[head * HID + n * 8 + 2 * c + 1];
    }

    float acc[2][4][4];
#pragma unroll
    for (int m = 0; m < 2; m++)
#pragma unroll
        for (int n = 0; n < 4; n++)
#pragma unroll
            for (int j = 0; j < 4; j++) acc[m][n][j] = 0.f;

    for (int k0 = 0; k0 < 512; k0 += 64) {
#pragma unroll
        for (int it = 0; it < 4; it++) {
            int idx = it * 256 + tid;
            int row = idx >> 3, c8 = (idx & 7) << 3;
            uint4 v = make_uint4(0u, 0u, 0u, 0u);
            if (bm + row < NN)
                v = *(const uint4*)(g_a1 + (size_t)(bm + row) * 512 + k0 + c8);
            *(uint4*)&As[row * AST + c8] = v;
        }
#pragma unroll
        for (int it = 0; it < 2; it++) {
            int idx = it * 256 + tid;
            int n = idx >> 3, c8 = (idx & 7) << 3;
            *(uint4*)&Bs[n * AST + c8] =
                *(const uint4*)(g_w1t + (size_t)(bn + n) * 512 + k0 + c8);
        }
        __syncthreads();
#pragma unroll
        for (int kk = 0; kk < 64; kk += 16) {
            unsigned af[2][4], bf[4][2];
#pragma unroll
            for (int m = 0; m < 2; m++) {
                int row = wm * 32 + m * 16 + r;
                af[m][0] = *(unsigned*)&As[row * AST + kk + 2 * c];
                af[m][1] = *(unsigned*)&As[(row + 8) * AST + kk + 2 * c];
                af[m][2] = *(unsigned*)&As[row * AST + kk + 2 * c + 8];
                af[m][3] = *(unsigned*)&As[(row + 8) * AST + kk + 2 * c + 8];
            }
#pragma unroll
            for (int n = 0; n < 4; n++) {
                int col = wn * 32 + n * 8 + r;
                bf[n][0] = *(unsigned*)&Bs[col * AST + kk + 2 * c];
                bf[n][1] = *(unsigned*)&Bs[col * AST + kk + 2 * c + 8];
            }
#pragma unroll
            for (int m = 0; m < 2; m++)
#pragma unroll
                for (int n = 0; n < 4; n++) mma_bf16(acc[m][n], af[m], bf[n]);
        }
        __syncthreads();
    }

#pragma unroll
    for (int m = 0; m < 2; m++) {
        int row0 = bm + wm * 32 + m * 16 + r;
#pragma unroll
        for (int n = 0; n < 4; n++) {
            int col = bn + wn * 32 + n * 8 + 2 * c;
            if (row0 < NN)
                *(float2*)(g_xl1 + (size_t)row0 * C1 + col) = make_float2(acc[m][n][0], acc[m][n][1]);
            if (row0 + 8 < NN)
                *(float2*)(g_xl1 + (size_t)(row0 + 8) * C1 + col) = make_float2(acc[m][n][2], acc[m][n][3]);
        }
        float s0 = 0.f, s1 = 0.f, d0 = 0.f, d1 = 0.f;
#pragma unroll
        for (int n = 0; n < 4; n++) {
            s0 += acc[m][n][0] * aSv[n * 2] + acc[m][n][1] * aSv[n * 2 + 1];
            s1 += acc[m][n][2] * aSv[n * 2] + acc[m][n][3] * aSv[n * 2 + 1];
            d0 += acc[m][n][0] * aDv[n * 2] + acc[m][n][1] * aDv[n * 2 + 1];
            d1 += acc[m][n][2] * aDv[n * 2] + acc[m][n][3] * aDv[n * 2 + 1];
        }
#pragma unroll
        for (int o = 1; o <= 2; o <<= 1) {
            s0 += __shfl_xor_sync(0xffffffffu, s0, o);
            s1 += __shfl_xor_sync(0xffffffffu, s1, o);
            d0 += __shfl_xor_sync(0xffffffffu, d0, o);
            d1 += __shfl_xor_sync(0xffffffffu, d1, o);
        }
        if (c == 0) {
            if (row0 < NN)     { g_as1[row0 * HEADS + head] = s0;       g_ad1[row0 * HEADS + head] = d0; }
            if (row0 + 8 < NN) { g_as1[(row0 + 8) * HEADS + head] = s1; g_ad1[(row0 + 8) * HEADS + head] = d1; }
        }
    }
}

// ---------------- aggregation layer1: warp per node, single pass ----------------
__global__ void __launch_bounds__(256)
agg1_kernel(const float* __restrict__ b1) {
    int warp = (blockIdx.x * blockDim.x + threadIdx.x) >> 5;
    if (warp >= NN) return;
    int lane = threadIdx.x & 31;
    int node = warp;
    int start = g_rowptr[node];
    int end   = g_rowptr[node + 1];
    int myh = lane >> 2;
    int c0 = lane * 8;

    float ad = g_ad1[(size_t)node * HEADS + myh];
    float es = __expf(lrelu(g_as1[(size_t)node * HEADS + myh] + ad));

    float acc[8];
    float ssum = es;
    {
        const float4* xp = (const float4*)(g_xl1 + (size_t)node * C1 + c0);
        float4 v0 = xp[0], v1 = xp[1];
        acc[0] = es*v0.x; acc[1] = es*v0.y; acc[2] = es*v0.z; acc[3] = es*v0.w;
        acc[4] = es*v1.x; acc[5] = es*v1.y; acc[6] = es*v1.z; acc[7] = es*v1.w;
    }
#pragma unroll 4
    for (int idx = start; idx < end; idx++) {
        int s = g_col[idx];
        float e = __expf(lrelu(g_as1[(size_t)s * HEADS + myh] + ad));
        const float4* xp = (const float4*)(g_xl1 + (size_t)s * C1 + c0);
        float4 v0 = xp[0], v1 = xp[1];
        acc[0] += e*v0.x; acc[1] += e*v0.y; acc[2] += e*v0.z; acc[3] += e*v0.w;
        acc[4] += e*v1.x; acc[5] += e*v1.y; acc[6] += e*v1.z; acc[7] += e*v1.w;
        ssum += e;
    }
    float inv = 1.f / (ssum + EPSV);
    float ov[8];
#pragma unroll
    for (int j = 0; j < 8; j++) {
        float v = acc[j] * inv + b1[c0 + j];
        ov[j] = v > 0.f ? v : (__expf(v) - 1.f);
    }
    float4* hp = (float4*)(g_h1 + (size_t)node * C1 + c0);
    hp[0] = make_float4(ov[0], ov[1], ov[2], ov[3]);
    hp[1] = make_float4(ov[4], ov[5], ov[6], ov[7]);
}

// ---------------- GEMM2: warp per row, W2 in smem, fused logits2 ----------------
// out[row][c] = sum_k h[row][k] * W2[k][c];  lane owns k in [lane*8, lane*8+8)
#define W2PAD 17
__global__ void __launch_bounds__(256)
gemm2_kernel(const float* __restrict__ W2,
             const float* __restrict__ att_s2,
             const float* __restrict__ att_d2) {
    __shared__ float Ws[256 * W2PAD];      // [k][16] padded to 17
    __shared__ float sa[16], sd[16];
    int tid = threadIdx.x;
    int warp = tid >> 5, lane = tid & 31;
    for (int i = tid; i < 4096; i += 256) {
        int k = i >> 4, c = i & 15;
        Ws[k * W2PAD + c] = W2[i];
    }
    if (tid < 16) { sa[tid] = att_s2[tid]; sd[tid] = att_d2[tid]; }
    __syncthreads();

    int row = blockIdx.x * 8 + warp;
    if (row >= NN) return;

    float4 h0 = *(const float4*)(g_h1 + (size_t)row * C1 + lane * 8);
    float4 h1 = *(const float4*)(g_h1 + (size_t)row * C1 + lane * 8 + 4);
    float hv[8] = {h0.x, h0.y, h0.z, h0.w, h1.x, h1.y, h1.z, h1.w};

    float p[16];
#pragma unroll
    for (int c = 0; c < 16; c++) p[c] = 0.f;
#pragma unroll
    for (int j = 0; j < 8; j++) {
        const float* wr = &Ws[(lane * 8 + j) * W2PAD];
        float4 w0 = *(const float4*)(wr + 0);
        float4 w1 = *(const float4*)(wr + 4);
        float4 w2 = *(const float4*)(wr + 8);
        float4 w3 = *(const float4*)(wr + 12);
        float h = hv[j];
        p[0]  += h * w0.x; p[1]  += h * w0.y; p[2]  += h * w0.z; p[3]  += h * w0.w;
        p[4]  += h * w1.x; p[5]  += h * w1.y; p[6]  += h * w1.z; p[7]  += h * w1.w;
        p[8]  += h * w2.x; p[9]  += h * w2.y; p[10] += h * w2.z; p[11] += h * w2.w;
        p[12] += h * w3.x; p[13] += h * w3.y; p[14] += h * w3.z; p[15] += h * w3.w;
    }
#pragma unroll
    for (int o = 16; o; o >>= 1)
#pragma unroll
        for (int c = 0; c < 16; c++) p[c] += __shfl_xor_sync(0xffffffffu, p[c], o);

    if (lane < 16) {
        // avoid runtime register indexing: select
        float myv = 0.f;
#pragma unroll
        for (int c = 0; c < 16; c++) if (c == lane) myv = p[c];
        g_xl2[(size_t)row * OUTC + lane] = myv;
    }
    if (lane == 0) {
        float vs = 0.f, vd = 0.f;
#pragma unroll
        for (int c = 0; c < 16; c++) { vs += p[c] * sa[c]; vd += p[c] * sd[c]; }
        g_as2[row] = vs;
        g_ad2[row] = vd;
    }
}

// ---------------- aggregation layer2: single pass ----------------
__global__ void __launch_bounds__(256)
agg2_kernel(const float* __restrict__ b2, float* __restrict__ out) {
    int warp = (blockIdx.x * blockDim.x + threadIdx.x) >> 5;
    if (warp >= NN) return;
    int lane = threadIdx.x & 31;
    int node = warp;
    int start = g_rowptr[node];
    int end   = g_rowptr[node + 1];

    float ad = g_ad2[node];
    int c = lane & 15;
    int half = lane >> 4;

    float acc = 0.f, ssum = 0.f;
    if (half == 0) {
        float es = __expf(lrelu(g_as2[node] + ad));
        acc = es * g_xl2[(size_t)node * OUTC + c];
        ssum = es;
    }
#pragma unroll 4
    for (int idx = start + half; idx < end; idx += 2) {
        int s = g_col[idx];
        float e = __expf(lrelu(g_as2[s] + ad));
        acc += e * g_xl2[(size_t)s * OUTC + c];
        ssum += e;
    }
    acc  += __shfl_down_sync(0xffffffffu, acc, 16);
    ssum += __shfl_down_sync(0xffffffffu, ssum, 16);
    if (lane < 16) out[(size_t)node * OUTC + c] = acc / (ssum + EPSV) + b2[c];
}

// ---------------- launch ----------------
extern "C" void kernel_launch(void* const* d_in, const int* in_sizes, int n_in,
                              void* d_out, int out_size) {
    const float* x     = (const float*)d_in[0];
    const int*   ei    = (const int*)d_in[1];
    const float* W1    = (const float*)d_in[2];
    const float* atts1 = (const float*)d_in[3];
    const float* attd1 = (const float*)d_in[4];
    const float* b1    = (const float*)d_in[5];
    const float* W2    = (const float*)d_in[6];
    const float* atts2 = (const float*)d_in[7];
    const float* attd2 = (const float*)d_in[8];
    const float* b2    = (const float*)d_in[9];
    float* out = (float*)d_out;

    zero_deg_kernel<<<64, 256>>>();                                   // 0
    hist_kernel<<<(EE + 255) / 256, 256>>>(ei);                       // 1
    prep_xw_kernel<<<(NN * INC + INC * C1 + 255) / 256, 256>>>(x, W1);// 2
    gemm1_mma_kernel<<<dim3((NN + 127) / 128, 4), 256>>>(atts1, attd1);// 3 <- profiled slot
    scan_kernel<<<1, 1024>>>();                                       // 4
    scatter_kernel<<<(EE + 255) / 256, 256>>>(ei);                    // 5
    agg1_kernel<<<(NN + 7) / 8, 256>>>(b1);                           // 6
    gemm2_kernel<<<(NN + 7) / 8, 256>>>(W2, atts2, attd2);            // 7
    agg2_kernel<<<(NN + 7) / 8, 256>>>(b2, out);                      // 8
}

// round 9
// speedup vs baseline: 1.0039x; 1.0039x over previous
#include <cuda_runtime.h>
#include <cuda_bf16.h>

// Problem constants
#define NN    50000
#define EE    800000
#define INC   128
#define HEADS 8
#define HID   32
#define C1    256
#define OUTC  16
#define NEG   0.2f
#define EPSV  1e-16f
#define KSPLIT 384     // [Xh|Xl|Xh] x [Wh|Wh|Wl]  (XlWl term dropped)

// ---------------- scratch ----------------
__device__ float g_xl1[NN * C1];
__device__ float g_h1 [NN * C1];
__device__ float g_as1[NN * HEADS];
__device__ float g_ad1[NN * HEADS];
__device__ float g_xl2[NN * OUTC];
__device__ float g_as2[NN];
__device__ float g_ad2[NN];
__device__ int   g_deg[NN];
__device__ int   g_rowptr[NN + 1];
__device__ int   g_cursor[NN];
__device__ int   g_col[EE];
__device__ __nv_bfloat16 g_a1 [NN * KSPLIT];
__device__ __nv_bfloat16 g_w1t[C1 * KSPLIT];

// ---------------- CSR build ----------------
__global__ void zero_deg_kernel() {
    int i = blockIdx.x * blockDim.x + threadIdx.x;
    for (; i < NN; i += gridDim.x * blockDim.x) g_deg[i] = 0;
}

__global__ void hist_kernel(const int* __restrict__ ei) {
    int i = blockIdx.x * blockDim.x + threadIdx.x;
    if (i < EE) atomicAdd(&g_deg[ei[EE + i]], 1);
}

__global__ void scan_kernel() {
    __shared__ int ssum[1024];
    const int T = 1024;
    int t = threadIdx.x;
    int chunk = (NN + T - 1) / T;
    int b = t * chunk;
    int e = b + chunk; if (e > NN) e = NN;
    int s = 0;
    for (int i = b; i < e; i++) s += g_deg[i];
    ssum[t] = s;
    __syncthreads();
    for (int off = 1; off < T; off <<= 1) {
        int v = (t >= off) ? ssum[t - off] : 0;
        __syncthreads();
        ssum[t] += v;
        __syncthreads();
    }
    int offset = (t == 0) ? 0 : ssum[t - 1];
    if (t == 0) g_rowptr[0] = 0;
    int run = offset;
    for (int i = b; i < e; i++) {
        g_cursor[i] = run;
        run += g_deg[i];
        g_rowptr[i + 1] = run;
    }
}

__global__ void scatter_kernel(const int* __restrict__ ei) {
    int i = blockIdx.x * blockDim.x + threadIdx.x;
    if (i < EE) {
        int d = ei[EE + i];
        int pos = atomicAdd(&g_cursor[d], 1);
        g_col[pos] = ei[i];
    }
}

__device__ __forceinline__ float lrelu(float x) { return x > 0.f ? x : NEG * x; }

// ---------------- fused bf16 split prep ----------------
__global__ void prep_xw_kernel(const float* __restrict__ x, const float* __restrict__ W1) {
    int i = blockIdx.x * blockDim.x + threadIdx.x;
    if (i < NN * INC) {
        int n = i >> 7, k = i & 127;
        float v = x[i];
        __nv_bfloat16 hi = __float2bfloat16(v);
        __nv_bfloat16 lo = __float2bfloat16(v - __bfloat162float(hi));
        __nv_bfloat16* p = g_a1 + (size_t)n * KSPLIT + k;
        p[0]   = hi;
        p[128] = lo;
        p[256] = hi;
    } else {
        int j = i - NN * INC;
        if (j < INC * C1) {
            int k = j >> 8, n = j & 255;
            float v = W1[j];
            __nv_bfloat16 hi = __float2bfloat16(v);
            __nv_bfloat16 lo = __float2bfloat16(v - __bfloat162float(hi));
            __nv_bfloat16* p = g_w1t + (size_t)n * KSPLIT + k;
            p[0]   = hi;
            p[128] = hi;
            p[256] = lo;
        }
    }
}

// ---------------- MMA helpers ----------------
__device__ __forceinline__ void mma_bf16(float* d, const unsigned* a, const unsigned* b) {
    asm volatile(
        "mma.sync.aligned.m16n8k16.row.col.f32.bf16.bf16.f32 "
        "{%0,%1,%2,%3}, {%4,%5,%6,%7}, {%8,%9}, {%0,%1,%2,%3};\n"
        : "+f"(d[0]), "+f"(d[1]), "+f"(d[2]), "+f"(d[3])
        : "r"(a[0]), "r"(a[1]), "r"(a[2]), "r"(a[3]), "r"(b[0]), "r"(b[1]));
}

__device__ __forceinline__ void ldsm_x4(unsigned& r0, unsigned& r1, unsigned& r2, unsigned& r3,
                                        unsigned addr) {
    asm volatile("ldmatrix.sync.aligned.m8n8.x4.shared.b16 {%0,%1,%2,%3}, [%4];\n"
                 : "=r"(r0), "=r"(r1), "=r"(r2), "=r"(r3) : "r"(addr));
}

// ---------------- GEMM1 via tensor cores (ldmatrix) + fused attention logits ----------------
#define AST 72
__global__ void __launch_bounds__(256, 2)
gemm1_mma_kernel(const float* __restrict__ attS, const float* __restrict__ attD) {
    __shared__ __nv_bfloat16 As[128 * AST];
    __shared__ __nv_bfloat16 Bs[64 * AST];
    int tid = threadIdx.x;
    int warp = tid >> 5, lane = tid & 31;
    int wm = warp >> 1, wn = warp & 1;
    int bm = blockIdx.x * 128, bn = blockIdx.y * 64;
    int r = lane >> 2, c = lane & 3;
    int head = (bn + wn * 32) >> 5;

    float aSv[8], aDv[8];
#pragma unroll
    for (int n = 0; n < 4; n++) {
        aSv[n * 2]     = attS[head * HID + n * 8 + 2 * c];
        aSv[n * 2 + 1] = attS[head * HID + n * 8 + 2 * c + 1];
        aDv[n * 2]     = attD[head * HID + n * 8 + 2 * c];
        aDv[n * 2 + 1] = attD[head * HID + n * 8 + 2 * c + 1];
    }

    unsigned a_addr = (unsigned)__cvta_generic_to_shared(As) +
        (unsigned)(((wm * 32 + (lane & 7) + ((lane >> 3) & 1) * 8) * AST + (lane >> 4) * 8) * 2);
    unsigned b_addr = (unsigned)__cvta_generic_to_shared(Bs) +
        (unsigned)(((wn * 32 + (lane & 7) + (lane >> 4) * 8) * AST + ((lane >> 3) & 1) * 8) * 2);

    float acc[2][4][4];
#pragma unroll
    for (int m = 0; m < 2; m++)
#pragma unroll
        for (int n = 0; n < 4; n++)
#pragma unroll
            for (int j = 0; j < 4; j++) acc[m][n][j] = 0.f;

    for (int k0 = 0; k0 < KSPLIT; k0 += 64) {
#pragma unroll
        for (int it = 0; it < 4; it++) {
            int idx = it * 256 + tid;
            int row = idx >> 3, c8 = (idx & 7) << 3;
            uint4 v = make_uint4(0u, 0u, 0u, 0u);
            if (bm + row < NN)
                v = *(const uint4*)(g_a1 + (size_t)(bm + row) * KSPLIT + k0 + c8);
            *(uint4*)&As[row * AST + c8] = v;
        }
#pragma unroll
        for (int it = 0; it < 2; it++) {
            int idx = it * 256 + tid;
            int n = idx >> 3, c8 = (idx & 7) << 3;
            *(uint4*)&Bs[n * AST + c8] =
                *(const uint4*)(g_w1t + (size_t)(bn + n) * KSPLIT + k0 + c8);
        }
        __syncthreads();
#pragma unroll
        for (int kk = 0; kk < 64; kk += 16) {
            unsigned af[2][4], bf[4][2];
            ldsm_x4(af[0][0], af[0][1], af[0][2], af[0][3], a_addr + kk * 2);
            ldsm_x4(af[1][0], af[1][1], af[1][2], af[1][3], a_addr + (16 * AST + kk) * 2);
            ldsm_x4(bf[0][0], bf[0][1], bf[1][0], bf[1][1], b_addr + kk * 2);
            ldsm_x4(bf[2][0], bf[2][1], bf[3][0], bf[3][1], b_addr + (16 * AST + kk) * 2);
#pragma unroll
            for (int m = 0; m < 2; m++)
#pragma unroll
                for (int n = 0; n < 4; n++) mma_bf16(acc[m][n], af[m], bf[n]);
        }
        __syncthreads();
    }

    // epilogue: xl1 stores + fused attention logits
#pragma unroll
    for (int m = 0; m < 2; m++) {
        int row0 = bm + wm * 32 + m * 16 + r;
#pragma unroll
        for (int n = 0; n < 4; n++) {
            int col = bn + wn * 32 + n * 8 + 2 * c;
            if (row0 < NN)
                *(float2*)(g_xl1 + (size_t)row0 * C1 + col) = make_float2(acc[m][n][0], acc[m][n][1]);
            if (row0 + 8 < NN)
                *(float2*)(g_xl1 + (size_t)(row0 + 8) * C1 + col) = make_float2(acc[m][n][2], acc[m][n][3]);
        }
        float s0 = 0.f, s1 = 0.f, d0 = 0.f, d1 = 0.f;
#pragma unroll
        for (int n = 0; n < 4; n++) {
            s0 += acc[m][n][0] * aSv[n * 2] + acc[m][n][1] * aSv[n * 2 + 1];
            s1 += acc[m][n][2] * aSv[n * 2] + acc[m][n][3] * aSv[n * 2 + 1];
            d0 += acc[m][n][0] * aDv[n * 2] + acc[m][n][1] * aDv[n * 2 + 1];
            d1 += acc[m][n][2] * aDv[n * 2] + acc[m][n][3] * aDv[n * 2 + 1];
        }
#pragma unroll
        for (int o = 1; o <= 2; o <<= 1) {
            s0 += __shfl_xor_sync(0xffffffffu, s0, o);
            s1 += __shfl_xor_sync(0xffffffffu, s1, o);
            d0 += __shfl_xor_sync(0xffffffffu, d0, o);
            d1 += __shfl_xor_sync(0xffffffffu, d1, o);
        }
        if (c == 0) {
            if (row0 < NN)     { g_as1[row0 * HEADS + head] = s0;       g_ad1[row0 * HEADS + head] = d0; }
            if (row0 + 8 < NN) { g_as1[(row0 + 8) * HEADS + head] = s1; g_ad1[(row0 + 8) * HEADS + head] = d1; }
        }
    }
}

// ---------------- aggregation layer1: warp per node, chunk-4 shared-exp ----------------
__global__ void __launch_bounds__(256)
agg1_kernel(const float* __restrict__ b1) {
    int warp = (blockIdx.x * blockDim.x + threadIdx.x) >> 5;
    if (warp >= NN) return;
    int lane = threadIdx.x & 31;
    int node = warp;
    int start = g_rowptr[node];
    int end   = g_rowptr[node + 1];
    int myh = lane >> 2;
    int l4  = lane & 3;
    int c0  = lane * 8;

    float ad = g_ad1[(size_t)node * HEADS + myh];
    float es = __expf(lrelu(g_as1[(size_t)node * HEADS + myh] + ad));

    float acc[8];
    float ssum = es;
    {
        const float4* xp = (const float4*)(g_xl1 + (size_t)node * C1 + c0);
        float4 v0 = xp[0], v1 = xp[1];
        acc[0] = es*v0.x; acc[1] = es*v0.y; acc[2] = es*v0.z; acc[3] = es*v0.w;
        acc[4] = es*v1.x; acc[5] = es*v1.y; acc[6] = es*v1.z; acc[7] = es*v1.w;
    }

    for (int idx = start; idx < end; idx += 4) {
        int rem = end - idx; if (rem > 4) rem = 4;      // warp-uniform
        int myl = l4 < rem ? l4 : 0;
        int s = g_col[idx + myl];
        float e = (l4 < rem) ? __expf(lrelu(g_as1[(size_t)s * HEADS + myh] + ad)) : 0.f;
        int g = lane & ~3;
#pragma unroll
        for (int j = 0; j < 4; j++) {
            if (j >= rem) break;                        // uniform break
            float ej = __shfl_sync(0xffffffffu, e, g + j);
            int   sj = __shfl_sync(0xffffffffu, s, g + j);
            const float4* xp = (const float4*)(g_xl1 + (size_t)sj * C1 + c0);
            float4 v0 = xp[0], v1 = xp[1];
            acc[0] += ej*v0.x; acc[1] += ej*v0.y; acc[2] += ej*v0.z; acc[3] += ej*v0.w;
            acc[4] += ej*v1.x; acc[5] += ej*v1.y; acc[6] += ej*v1.z; acc[7] += ej*v1.w;
            ssum += ej;
        }
    }
    float inv = 1.f / (ssum + EPSV);
    float ov[8];
#pragma unroll
    for (int j = 0; j < 8; j++) {
        float v = acc[j] * inv + b1[c0 + j];
        ov[j] = v > 0.f ? v : (__expf(v) - 1.f);
    }
    float4* hp = (float4*)(g_h1 + (size_t)node * C1 + c0);
    hp[0] = make_float4(ov[0], ov[1], ov[2], ov[3]);
    hp[1] = make_float4(ov[4], ov[5], ov[6], ov[7]);
}

// ---------------- GEMM2: warp per row, W2 in smem, fused logits2 ----------------
#define W2PAD 17
__global__ void __launch_bounds__(256)
gemm2_kernel(const float* __restrict__ W2,
             const float* __restrict__ att_s2,
             const float* __restrict__ att_d2) {
    __shared__ float Ws[256 * W2PAD];
    __shared__ float sa[16], sd[16];
    int tid = threadIdx.x;
    int warp = tid >> 5, lane = tid & 31;
    for (int i = tid; i < 4096; i += 256) {
        int k = i >> 4, c = i & 15;
        Ws[k * W2PAD + c] = W2[i];
    }
    if (tid < 16) { sa[tid] = att_s2[tid]; sd[tid] = att_d2[tid]; }
    __syncthreads();

    int row = blockIdx.x * 8 + warp;
    if (row >= NN) return;

    float4 h0 = *(const float4*)(g_h1 + (size_t)row * C1 + lane * 8);
    float4 h1 = *(const float4*)(g_h1 + (size_t)row * C1 + lane * 8 + 4);
    float hv[8] = {h0.x, h0.y, h0.z, h0.w, h1.x, h1.y, h1.z, h1.w};

    float p[16];
#pragma unroll
    for (int c = 0; c < 16; c++) p[c] = 0.f;
#pragma unroll
    for (int j = 0; j < 8; j++) {
        const float* wr = &Ws[(lane * 8 + j) * W2PAD];
        float4 w0 = *(const float4*)(wr + 0);
        float4 w1 = *(const float4*)(wr + 4);
        float4 w2 = *(const float4*)(wr + 8);
        float4 w3 = *(const float4*)(wr + 12);
        float h = hv[j];
        p[0]  += h * w0.x; p[1]  += h * w0.y; p[2]  += h * w0.z; p[3]  += h * w0.w;
        p[4]  += h * w1.x; p[5]  += h * w1.y; p[6]  += h * w1.z; p[7]  += h * w1.w;
        p[8]  += h * w2.x; p[9]  += h * w2.y; p[10] += h * w2.z; p[11] += h * w2.w;
        p[12] += h * w3.x; p[13] += h * w3.y; p[14] += h * w3.z; p[15] += h * w3.w;
    }
#pragma unroll
    for (int o = 16; o; o >>= 1)
#pragma unroll
        for (int c = 0; c < 16; c++) p[c] += __shfl_xor_sync(0xffffffffu, p[c], o);

    if (lane < 16) {
        float myv = 0.f;
#pragma unroll
        for (int c = 0; c < 16; c++) if (c == lane) myv = p[c];
        g_xl2[(size_t)row * OUTC + lane] = myv;
    }
    if (lane == 0) {
        float vs = 0.f, vd = 0.f;
#pragma unroll
        for (int c = 0; c < 16; c++) { vs += p[c] * sa[c]; vd += p[c] * sd[c]; }
        g_as2[row] = vs;
        g_ad2[row] = vd;
    }
}

// ---------------- aggregation layer2: chunk-16 shared-exp, UNIFORM inner loop ----------------
__global__ void __launch_bounds__(256)
agg2_kernel(const float* __restrict__ b2, float* __restrict__ out) {
    int warp = (blockIdx.x * blockDim.x + threadIdx.x) >> 5;
    if (warp >= NN) return;
    int lane = threadIdx.x & 31;
    int node = warp;
    int start = g_rowptr[node];
    int end   = g_rowptr[node + 1];

    float ad = g_ad2[node];
    int c = lane & 15;
    int half = lane >> 4;
    int l16 = lane & 15;

    float acc = 0.f, ssum = 0.f;
    if (half == 0) {
        float es = __expf(lrelu(g_as2[node] + ad));
        acc = es * g_xl2[(size_t)node * OUTC + c];
        ssum = es;
    }
    for (int idx = start; idx < end; idx += 16) {
        int rem = end - idx; if (rem > 16) rem = 16;    // warp-uniform
        int myl = l16 < rem ? l16 : 0;
        int s = g_col[idx + myl];
        float e = (l16 < rem) ? __expf(lrelu(g_as2[s] + ad)) : 0.f;
        // UNIFORM loop: every lane executes every j; accumulate predicated by parity.
        for (int j = 0; j < rem; j++) {
            float ej = __shfl_sync(0xffffffffu, e, j);
            int   sj = __shfl_sync(0xffffffffu, s, j);
            if ((j & 1) == half) {
                acc += ej * g_xl2[(size_t)sj * OUTC + c];
                ssum += ej;
            }
        }
    }
    acc  += __shfl_down_sync(0xffffffffu, acc, 16);
    ssum += __shfl_down_sync(0xffffffffu, ssum, 16);
    if (lane < 16) out[(size_t)node * OUTC + c] = acc / (ssum + EPSV) + b2[c];
}

// ---------------- launch ----------------
extern "C" void kernel_launch(void* const* d_in, const int* in_sizes, int n_in,
                              void* d_out, int out_size) {
    const float* x     = (const float*)d_in[0];
    const int*   ei    = (const int*)d_in[1];
    const float* W1    = (const float*)d_in[2];
    const float* atts1 = (const float*)d_in[3];
    const float* attd1 = (const float*)d_in[4];
    const float* b1    = (const float*)d_in[5];
    const float* W2    = (const float*)d_in[6];
    const float* atts2 = (const float*)d_in[7];
    const float* attd2 = (const float*)d_in[8];
    const float* b2    = (const float*)d_in[9];
    float* out = (float*)d_out;

    zero_deg_kernel<<<64, 256>>>();                                    // 0
    hist_kernel<<<(EE + 255) / 256, 256>>>(ei);                        // 1
    prep_xw_kernel<<<(NN * INC + INC * C1 + 255) / 256, 256>>>(x, W1); // 2
    gemm1_mma_kernel<<<dim3((NN + 127) / 128, 4), 256>>>(atts1, attd1);// 3 <- profiled slot
    scan_kernel<<<1, 1024>>>();                                        // 4
    scatter_kernel<<<(EE + 255) / 256, 256>>>(ei);                     // 5
    agg1_kernel<<<(NN + 7) / 8, 256>>>(b1);                            // 6
    gemm2_kernel<<<(NN + 7) / 8, 256>>>(W2, atts2, attd2);             // 7
    agg2_kernel<<<(NN + 7) / 8, 256>>>(b2, out);                       // 8
}